// round 12
// baseline (speedup 1.0000x reference)
#include <cuda_runtime.h>
#include <cuda_fp16.h>
#include <cstdint>

#define S_ 4
#define B_ 2
#define N_ 1024
#define D_ 1024
#define H_ 16
#define DH_ 64

// ---------------- device scratch (no allocations allowed) -------------------
__device__ __half g_xh[B_ * N_ * D_];                       // 4MB
__device__ __half g_wh[13 * 1024 * 1024];                   // Wq(0-3) Wk(4-7) Wv(8-11) Wo(12)
__device__ __half g_qh[S_ * B_ * N_ * D_];                  // 16MB
__device__ __half g_kh[S_ * B_ * N_ * D_];                  // 16MB
__device__ __half g_vh[S_ * B_ * N_ * D_];                  // 16MB
__device__ __half g_combh[B_ * N_ * D_];                    // 4MB
__device__ float g_meanx[B_ * D_];
__device__ float g_scalars[16];  // [0..7]=gw*coh (b*4+s), [8..11]=gw/H, [12]=scale/temp

// ---------------- helpers ----------------------------------------------------
__device__ __forceinline__ uint32_t smem_u32(const void* p) {
    uint32_t a;
    asm("{ .reg .u64 t; cvta.to.shared.u64 t, %1; cvt.u32.u64 %0, t; }" : "=r"(a) : "l"(p));
    return a;
}
__device__ __forceinline__ void cp16h(uint32_t dst, const __half* src) {
    asm volatile("cp.async.ca.shared.global [%0], [%1], 16;" :: "r"(dst), "l"(src) : "memory");
}
__device__ __forceinline__ void ldm4(uint32_t* r, uint32_t addr) {
    asm volatile("ldmatrix.sync.aligned.m8n8.x4.shared.b16 {%0,%1,%2,%3}, [%4];"
        : "=r"(r[0]), "=r"(r[1]), "=r"(r[2]), "=r"(r[3]) : "r"(addr));
}
__device__ __forceinline__ void ldm2t(uint32_t* r, uint32_t addr) {
    asm volatile("ldmatrix.sync.aligned.m8n8.x2.trans.shared.b16 {%0,%1}, [%2];"
        : "=r"(r[0]), "=r"(r[1]) : "r"(addr));
}
__device__ __forceinline__ void mma16816(float* d, const uint32_t* a, uint32_t b0, uint32_t b1) {
    asm volatile(
        "mma.sync.aligned.m16n8k16.row.col.f32.f16.f16.f32 "
        "{%0,%1,%2,%3}, {%4,%5,%6,%7}, {%8,%9}, {%0,%1,%2,%3};"
        : "+f"(d[0]), "+f"(d[1]), "+f"(d[2]), "+f"(d[3])
        : "r"(a[0]), "r"(a[1]), "r"(a[2]), "r"(a[3]), "r"(b0), "r"(b1));
}
__device__ __forceinline__ uint32_t h2u(__half2 h) { return *(uint32_t*)&h; }
__device__ __forceinline__ __half2 u2h(uint32_t u) { return *(__half2*)&u; }

// ---------------- merged prep (fp16 round) + colmean -------------------------
__global__ void prepcol_k(const float* __restrict__ x, const float* __restrict__ Wq,
                          const float* __restrict__ Wk, const float* __restrict__ Wv,
                          const float* __restrict__ Wo) {
    __shared__ float part[8][33];
    if (blockIdx.x < 15360) {
        long long idx = ((long long)blockIdx.x * 256 + threadIdx.x) * 4;
        const float* src; __half* dst; long long off;
        if (idx < 2097152)        { src = x;  off = idx;            dst = g_xh; }
        else if (idx < 6291456)   { src = Wq; off = idx - 2097152;  dst = g_wh; }
        else if (idx < 10485760)  { src = Wk; off = idx - 6291456;  dst = g_wh + 4194304; }
        else if (idx < 14680064)  { src = Wv; off = idx - 10485760; dst = g_wh + 8388608; }
        else                      { src = Wo; off = idx - 14680064; dst = g_wh + 12582912; }
        float4 v = *(const float4*)(src + off);
        __half2 h0 = __floats2half2_rn(v.x, v.y), h1 = __floats2half2_rn(v.z, v.w);
        uint2 o; o.x = h2u(h0); o.y = h2u(h1);
        *(uint2*)(dst + off) = o;
    } else {
        int bid = blockIdx.x - 15360;
        int col = bid * 32 + (threadIdx.x & 31);
        int chunk = threadIdx.x >> 5;
        int b = col >> 10, d = col & 1023;
        float sum = 0.f;
        const float* xp = x + (long long)b * N_ * D_ + d + (long long)(chunk * 128) * D_;
        #pragma unroll 8
        for (int n = 0; n < 128; n++) sum += xp[(long long)n * D_];
        part[chunk][threadIdx.x & 31] = sum;
        __syncthreads();
        if (threadIdx.x < 32) {
            float s = 0.f;
            #pragma unroll
            for (int c = 0; c < 8; c++) s += part[c][threadIdx.x];
            g_meanx[bid * 32 + threadIdx.x] = s * (1.0f / N_);
        }
    }
}

// ---------------- gate: coh, gw, fused scalars ------------------------------
__global__ void gate_k(const float* __restrict__ Wg, const float* __restrict__ bg,
                       const float* __restrict__ hyp_w, const float* __restrict__ temp_p) {
    __shared__ float cohs[8];
    int tid = threadIdx.x;
    int w = tid >> 5, lane = tid & 31;
    if (w < 8) {
        int b = w >> 2, s = w & 3;
        float sum = 0.f;
        for (int d = lane; d < D_; d += 32)
            sum += g_meanx[b * D_ + d] * Wg[s * D_ + d];
        for (int o = 16; o; o >>= 1) sum += __shfl_xor_sync(0xffffffffu, sum, o);
        if (lane == 0) cohs[w] = 1.0f / (1.0f + expf(-(sum + bg[s])));
    }
    __syncthreads();
    if (tid == 0) {
        float t = fminf(fmaxf(temp_p[0], 0.1f), 10.0f);
        float e[S_], mx = -1e30f;
        for (int s = 0; s < S_; s++) { e[s] = hyp_w[s] / t; mx = fmaxf(mx, e[s]); }
        float den = 0.f;
        for (int s = 0; s < S_; s++) { e[s] = expf(e[s] - mx); den += e[s]; }
        for (int s = 0; s < S_; s++) {
            float gw = e[s] / den;
            g_scalars[8 + s] = gw / (float)H_;
            for (int b = 0; b < B_; b++)
                g_scalars[b * 4 + s] = gw * cohs[b * 4 + s];
        }
        g_scalars[12] = 0.125f / t;   // DH^-0.5 / temp
    }
}

// ---------------- zero amean half of d_out -----------------------------------
__global__ void zero2_k(float* __restrict__ outp) {
    long long idx = ((long long)blockIdx.x * 256 + threadIdx.x) * 4;
    *(float4*)(outp + idx) = make_float4(0.f, 0.f, 0.f, 0.f);
}

// ---------------- fp16 HMMA GEMM (projections): 2-stage (R8-proven) ---------
template<int MODE>
__global__ void __launch_bounds__(256) hgemm_k(float* __restrict__ outp,
                                               const float* __restrict__ bias)
{
    constexpr int STAGE = 256 * 128;
    extern __shared__ char smem[];
    uint32_t smb = smem_u32(smem);

    int tid = threadIdx.x, lane = tid & 31, wid = tid >> 5;
    int warpM = wid & 3, warpN = wid >> 2;
    int n0 = blockIdx.x * 128, m0 = blockIdx.y * 128, z = blockIdx.z;

    const __half *Ag, *Bg;
    if (MODE == 0) { Ag = g_xh; Bg = g_wh + ((long long)z << 20); }
    else           { Ag = g_combh; Bg = g_wh + (12LL << 20); }

    float acc[2][8][4];
    #pragma unroll
    for (int mf = 0; mf < 2; mf++)
        #pragma unroll
        for (int nf = 0; nf < 8; nf++)
            #pragma unroll
            for (int i = 0; i < 4; i++) acc[mf][nf][i] = 0.f;

    auto issue = [&](int t) {
        const __half* ap = Ag + (long long)m0 * 1024 + t * 64;
        const __half* bp = Bg + (long long)n0 * 1024 + t * 64;
        uint32_t sa  = smb + (t & 1) * STAGE;
        uint32_t sbb = sa + 128 * 128;
        #pragma unroll
        for (int i = 0; i < 4; i++) {
            int c = tid + 256 * i, row = c >> 3, ch = c & 7;
            cp16h(sa + ((row * 128 + ch * 16) ^ ((row & 7) << 4)),
                  ap + (long long)row * 1024 + ch * 8);
        }
        #pragma unroll
        for (int i = 0; i < 4; i++) {
            int c = tid + 256 * i, row = c >> 3, ch = c & 7;
            cp16h(sbb + ((row * 128 + ch * 16) ^ ((row & 7) << 4)),
                  bp + (long long)row * 1024 + ch * 8);
        }
        asm volatile("cp.async.commit_group;" ::: "memory");
    };

    issue(0);
    for (int t = 0; t < 16; t++) {
        if (t + 1 < 16) {
            issue(t + 1);
            asm volatile("cp.async.wait_group 1;" ::: "memory");
        } else {
            asm volatile("cp.async.wait_group 0;" ::: "memory");
        }
        __syncthreads();
        uint32_t sa = smb + (t & 1) * STAGE, sbb = sa + 128 * 128;
        #pragma unroll
        for (int kk = 0; kk < 4; kk++) {
            uint32_t af[2][4], bf[4][4];
            #pragma unroll
            for (int mf = 0; mf < 2; mf++) {
                int row = warpM * 32 + mf * 16 + (lane & 15);
                uint32_t off = row * 128 + kk * 32 + ((lane >> 4) << 4);
                ldm4(af[mf], sa + (off ^ ((row & 7) << 4)));
            }
            #pragma unroll
            for (int nb = 0; nb < 4; nb++) {
                int row = warpN * 64 + nb * 16 + (lane & 15);
                uint32_t off = row * 128 + kk * 32 + ((lane >> 4) << 4);
                ldm4(bf[nb], sbb + (off ^ ((row & 7) << 4)));
            }
            #pragma unroll
            for (int mf = 0; mf < 2; mf++)
                #pragma unroll
                for (int nf = 0; nf < 8; nf++)
                    mma16816(acc[mf][nf], af[mf], bf[nf >> 1][nf & 1], bf[nf >> 1][(nf & 1) + 2]);
        }
        __syncthreads();
    }

    int r4 = lane >> 2, c4l = lane & 3;
    if (MODE == 0) {
        int w_ = z >> 2, s_ = z & 3;
        __half* C = (w_ == 0 ? g_qh : (w_ == 1 ? g_kh : g_vh)) + ((long long)s_ << 21);
        #pragma unroll
        for (int mf = 0; mf < 2; mf++)
            #pragma unroll
            for (int nf = 0; nf < 8; nf++)
                #pragma unroll
                for (int hf = 0; hf < 2; hf++) {
                    int row = m0 + warpM * 32 + mf * 16 + r4 + hf * 8;
                    int col = n0 + warpN * 64 + nf * 8 + c4l * 2;
                    __half2 hv = __floats2half2_rn(acc[mf][nf][hf * 2], acc[mf][nf][hf * 2 + 1]);
                    *(__half2*)(C + (long long)row * 1024 + col) = hv;
                }
    } else {
        #pragma unroll
        for (int mf = 0; mf < 2; mf++)
            #pragma unroll
            for (int nf = 0; nf < 8; nf++)
                #pragma unroll
                for (int hf = 0; hf < 2; hf++) {
                    int row = m0 + warpM * 32 + mf * 16 + r4 + hf * 8;
                    int col = n0 + warpN * 64 + nf * 8 + c4l * 2;
                    float2 o;
                    o.x = acc[mf][nf][hf * 2]     + bias[col];
                    o.y = acc[mf][nf][hf * 2 + 1] + bias[col + 1];
                    *(float2*)(outp + (long long)row * 1024 + col) = o;
                }
    }
}

// ---------------- fused attention v6: 6-slot ring + 512 threads --------------
// grid (32, 16, 2) = (it, h, b). smem layout identical to v5 (231,168 B).
#define AME_SCALE 256.0f
__global__ void __launch_bounds__(512) fused_attn6_k(float* __restrict__ amean_out) {
    extern __shared__ char smem[];
    uint32_t smb = smem_u32(smem);
    const uint32_t STRIP = smb;
    const uint32_t AMEH  = smb + 65536;
    const uint32_t RING  = smb + 131584;
    float* lred = (float*)(smem + 229888);
    float* linv = (float*)(smem + 231040);

    int tid = threadIdx.x, lane = tid & 31, wid = tid >> 5;
    int it = blockIdx.x, h = blockIdx.y, b = blockIdx.z;
    int i0 = it * 32;
    int r4 = lane >> 2, c4l = lane & 3, c2 = c4l * 2;

    // role split
    int mw = wid & 1, jw = wid >> 1;        // scores: m-half x j-block(16)
    int dgrp = wid & 3, jgrp = wid >> 2;    // PV: 16-col group x 32-j group

    for (int i = tid; i < 16512; i += 512)
        asm volatile("st.shared.b32 [%0], %1;" :: "r"(AMEH + i * 4), "r"(0u));
    __syncthreads();

    float alpha = g_scalars[12];
    float oacc[2][2][4];
    #pragma unroll
    for (int mf = 0; mf < 2; mf++)
        #pragma unroll
        for (int nb = 0; nb < 2; nb++)
            #pragma unroll
            for (int i = 0; i < 4; i++) oacc[mf][nb][i] = 0.f;

    // tile stream: g = s*17 + t; t=0 -> Q, 1..8 -> K(jt), 9..16 -> V(jt)
    auto issue_g = [&](int g) {
        if (g < 68) {
            int s = g / 17, t = g - s * 17;
            long long sbase = ((long long)(s * B_ + b)) << 20;
            uint32_t dst = RING + (uint32_t)(g % 6) * 16384;
            if (t == 0) {
                if (tid < 256) {
                    const __half* src = g_qh + sbase + (long long)i0 * 1024 + h * 64;
                    int r = tid >> 3, c = tid & 7;
                    cp16h(dst + ((r * 128 + c * 16) ^ ((r & 7) << 4)),
                          src + (long long)r * 1024 + c * 8);
                }
            } else {
                const __half* base = ((t <= 8) ? g_kh : g_vh) + sbase + h * 64;
                int jt = (t <= 8) ? (t - 1) : (t - 9);
                const __half* src = base + (long long)jt * 128 * 1024;
                #pragma unroll
                for (int i = 0; i < 2; i++) {
                    int idx = tid + 512 * i, r = idx >> 3, c = idx & 7;
                    cp16h(dst + ((r * 128 + c * 16) ^ ((r & 7) << 4)),
                          src + (long long)r * 1024 + c * 8);
                }
            }
        }
        asm volatile("cp.async.commit_group;" ::: "memory");
    };

    for (int g = 0; g < 5; g++) issue_g(g);
    int gi = 5;

    for (int s = 0; s < S_; s++) {
        float ga = g_scalars[8 + s], wsb = g_scalars[b * 4 + s];
        int gbase = s * 17;

        // ---- consume Q (this warp's m-half only) ----
        asm volatile("cp.async.wait_group 4;" ::: "memory");
        __syncthreads();
        issue_g(gi++);
        uint32_t qf[4][4];
        {
            uint32_t qslot = RING + (uint32_t)(gbase % 6) * 16384;
            #pragma unroll
            for (int kk = 0; kk < 4; kk++) {
                int r = mw * 16 + (lane & 15);
                ldm4(qf[kk], qslot + ((r * 128 + kk * 32 + ((lane >> 4) << 4)) ^ ((r & 7) << 4)));
            }
        }

        // ---- SCORE rounds ----
        float l_part[2] = {0.f, 0.f};
        for (int jt = 0; jt < 8; jt++) {
            asm volatile("cp.async.wait_group 4;" ::: "memory");
            __syncthreads();
            issue_g(gi++);
            uint32_t kb = RING + (uint32_t)((gbase + 1 + jt) % 6) * 16384;
            float sacc[2][4];
            #pragma unroll
            for (int nb = 0; nb < 2; nb++)
                #pragma unroll
                for (int i = 0; i < 4; i++) sacc[nb][i] = 0.f;
            #pragma unroll
            for (int kk = 0; kk < 4; kk++) {
                uint32_t bf[4];
                int r = jw * 16 + (lane & 15);
                ldm4(bf, kb + ((r * 128 + kk * 32 + ((lane >> 4) << 4)) ^ ((r & 7) << 4)));
                mma16816(sacc[0], qf[kk], bf[0], bf[2]);
                mma16816(sacc[1], qf[kk], bf[1], bf[3]);
            }
            #pragma unroll
            for (int nb = 0; nb < 2; nb++)
                #pragma unroll
                for (int hf = 0; hf < 2; hf++) {
                    float e0 = __expf(sacc[nb][hf * 2]     * alpha);
                    float e1 = __expf(sacc[nb][hf * 2 + 1] * alpha);
                    l_part[hf] += e0 + e1;
                    int row = mw * 16 + r4 + hf * 8;
                    uint32_t byte = (uint32_t)((jt * 128 + jw * 16 + nb * 8 + c2) * 2);
                    asm volatile("st.shared.b32 [%0], %1;"
                        :: "r"(STRIP + row * 2048 + (byte ^ ((row & 7) << 4))),
                           "r"(h2u(__floats2half2_rn(e0, e1))));
                }
        }

        // ---- l reduce ----
        #pragma unroll
        for (int i = 0; i < 2; i++) {
            l_part[i] += __shfl_xor_sync(0xffffffffu, l_part[i], 1);
            l_part[i] += __shfl_xor_sync(0xffffffffu, l_part[i], 2);
        }
        if (c4l == 0)
            #pragma unroll
            for (int i = 0; i < 2; i++) lred[(mw * 16 + i * 8 + r4) * 9 + jw] = l_part[i];
        __syncthreads();
        if (tid < 32) {
            float sm = 0.f;
            #pragma unroll
            for (int w = 0; w < 8; w++) sm += lred[tid * 9 + w];
            linv[tid] = 1.0f / sm;
        }
        __syncthreads();

        // per-s per-thread constants
        __half2 sc[2][2], gah[2][2];
        #pragma unroll
        for (int mf = 0; mf < 2; mf++) {
            float li0 = linv[mf * 16 + r4], li1 = linv[mf * 16 + r4 + 8];
            sc[mf][0]  = __float2half2_rn(wsb * li0);
            sc[mf][1]  = __float2half2_rn(wsb * li1);
            gah[mf][0] = __float2half2_rn(ga * li0 * AME_SCALE);
            gah[mf][1] = __float2half2_rn(ga * li1 * AME_SCALE);
        }

        // ---- PV rounds ----
        for (int jt = 0; jt < 8; jt++) {
            asm volatile("cp.async.wait_group 4;" ::: "memory");
            __syncthreads();
            issue_g(gi++);
            uint32_t vb = RING + (uint32_t)((gbase + 9 + jt) % 6) * 16384;
            #pragma unroll
            for (int kt = 0; kt < 2; kt++) {
                int jloc = jgrp * 32 + kt * 16;
                uint32_t af[2][4];
                #pragma unroll
                for (int mf = 0; mf < 2; mf++) {
                    int r = mf * 16 + (lane & 15);
                    uint32_t byte = (uint32_t)((jt * 128 + jloc) * 2) + ((lane >> 4) << 4);
                    ldm4(af[mf], STRIP + r * 2048 + (byte ^ ((r & 7) << 4)));
                }
                if (dgrp == 0) {
                    #pragma unroll
                    for (int mf = 0; mf < 2; mf++) {
                        int row0 = mf * 16 + r4, row1 = row0 + 8;
                        int colb = jt * 128 + jloc + c2;
                        uint32_t a00 = AMEH + (uint32_t)(row0 * 1032 + colb) * 2;
                        uint32_t a10 = AMEH + (uint32_t)(row1 * 1032 + colb) * 2;
                        uint32_t old;
                        asm volatile("ld.shared.b32 %0, [%1];" : "=r"(old) : "r"(a00));
                        asm volatile("st.shared.b32 [%0], %1;" :: "r"(a00),
                            "r"(h2u(__hfma2(u2h(af[mf][0]), gah[mf][0], u2h(old)))));
                        asm volatile("ld.shared.b32 %0, [%1];" : "=r"(old) : "r"(a10));
                        asm volatile("st.shared.b32 [%0], %1;" :: "r"(a10),
                            "r"(h2u(__hfma2(u2h(af[mf][1]), gah[mf][1], u2h(old)))));
                        asm volatile("ld.shared.b32 %0, [%1];" : "=r"(old) : "r"(a00 + 16));
                        asm volatile("st.shared.b32 [%0], %1;" :: "r"(a00 + 16),
                            "r"(h2u(__hfma2(u2h(af[mf][2]), gah[mf][0], u2h(old)))));
                        asm volatile("ld.shared.b32 %0, [%1];" : "=r"(old) : "r"(a10 + 16));
                        asm volatile("st.shared.b32 [%0], %1;" :: "r"(a10 + 16),
                            "r"(h2u(__hfma2(u2h(af[mf][3]), gah[mf][1], u2h(old)))));
                    }
                }
                #pragma unroll
                for (int mf = 0; mf < 2; mf++) {
                    af[mf][0] = h2u(__hmul2(u2h(af[mf][0]), sc[mf][0]));
                    af[mf][1] = h2u(__hmul2(u2h(af[mf][1]), sc[mf][1]));
                    af[mf][2] = h2u(__hmul2(u2h(af[mf][2]), sc[mf][0]));
                    af[mf][3] = h2u(__hmul2(u2h(af[mf][3]), sc[mf][1]));
                }
                uint32_t bf0[2], bf1[2];
                int kr = jloc + (lane & 7) + ((lane >> 3) & 1) * 8;
                ldm2t(bf0, vb + ((kr * 128 + dgrp * 32) ^ ((kr & 7) << 4)));
                ldm2t(bf1, vb + ((kr * 128 + dgrp * 32 + 16) ^ ((kr & 7) << 4)));
                #pragma unroll
                for (int mf = 0; mf < 2; mf++) {
                    mma16816(oacc[mf][0], af[mf], bf0[0], bf0[1]);
                    mma16816(oacc[mf][1], af[mf], bf1[0], bf1[1]);
                }
            }
        }
    } // s
    __syncthreads();

    // ---- O: reduce 4 jgrp partials via ring scratch ----
    {
        float* scr = (float*)(smem + 131584);
        if (jgrp > 0) {
            int base = ((jgrp - 1) * 4 + dgrp) * 512 + lane * 16;
            #pragma unroll
            for (int mf = 0; mf < 2; mf++)
                #pragma unroll
                for (int nb = 0; nb < 2; nb++)
                    #pragma unroll
                    for (int i = 0; i < 4; i++)
                        scr[base + mf * 8 + nb * 4 + i] = oacc[mf][nb][i];
        }
        __syncthreads();
        if (jgrp == 0) {
            #pragma unroll
            for (int mf = 0; mf < 2; mf++)
                #pragma unroll
                for (int nb = 0; nb < 2; nb++) {
                    #pragma unroll
                    for (int g = 1; g < 4; g++) {
                        int base = ((g - 1) * 4 + dgrp) * 512 + lane * 16;
                        #pragma unroll
                        for (int i = 0; i < 4; i++)
                            oacc[mf][nb][i] += scr[base + mf * 8 + nb * 4 + i];
                    }
                    #pragma unroll
                    for (int hf = 0; hf < 2; hf++) {
                        int row = i0 + mf * 16 + r4 + hf * 8;
                        int col = h * 64 + dgrp * 16 + nb * 8 + c2;
                        __half2 hv = __floats2half2_rn(oacc[mf][nb][hf * 2],
                                                       oacc[mf][nb][hf * 2 + 1]);
                        *(__half2*)(g_combh + ((long long)b << 20)
                                    + (long long)row * 1024 + col) = hv;
                    }
                }
        }
    }

    // ---- amean flush: fp16(x256) -> f32 red.add into d_out second half ----
    {
        const float inv_s = 1.0f / AME_SCALE;
        for (int i = tid; i < 8192; i += 512) {
            int row = i >> 8, cc = (i & 255) * 4;
            uint2 u;
            asm volatile("ld.shared.v2.b32 {%0,%1}, [%2];"
                : "=r"(u.x), "=r"(u.y) : "r"(AMEH + (uint32_t)(row * 1032 + cc) * 2));
            float2 f0 = __half22float2(u2h(u.x)), f1 = __half22float2(u2h(u.y));
            float* dst = amean_out + ((long long)(b * 1024 + i0 + row)) * 1024 + cc;
            asm volatile("red.global.add.f32 [%0], %1;" :: "l"(dst),     "f"(f0.x * inv_s));
            asm volatile("red.global.add.f32 [%0], %1;" :: "l"(dst + 1), "f"(f0.y * inv_s));
            asm volatile("red.global.add.f32 [%0], %1;" :: "l"(dst + 2), "f"(f1.x * inv_s));
            asm volatile("red.global.add.f32 [%0], %1;" :: "l"(dst + 3), "f"(f1.y * inv_s));
        }
    }
}

// ---------------- launch ----------------------------------------------------
extern "C" void kernel_launch(void* const* d_in, const int* in_sizes, int n_in,
                              void* d_out, int out_size) {
    const float* x     = (const float*)d_in[0];
    const float* Wq    = (const float*)d_in[1];
    const float* Wk    = (const float*)d_in[2];
    const float* Wv    = (const float*)d_in[3];
    const float* Wg    = (const float*)d_in[4];
    const float* bg    = (const float*)d_in[5];
    const float* Wo    = (const float*)d_in[6];
    const float* bo    = (const float*)d_in[7];
    const float* hyp_w = (const float*)d_in[8];
    const float* temp  = (const float*)d_in[9];
    float* out = (float*)d_out;
    float* out2 = out + (long long)B_ * N_ * D_;

    const int SM_PIPE  = 65536;
    const int SM_FUSED = 231168;

    cudaFuncSetAttribute(hgemm_k<0>, cudaFuncAttributeMaxDynamicSharedMemorySize, SM_PIPE);
    cudaFuncSetAttribute(hgemm_k<3>, cudaFuncAttributeMaxDynamicSharedMemorySize, SM_PIPE);
    cudaFuncSetAttribute(fused_attn6_k, cudaFuncAttributeMaxDynamicSharedMemorySize, SM_FUSED);

    prepcol_k<<<15424, 256>>>(x, Wq, Wk, Wv, Wo);
    gate_k<<<1, 256>>>(Wg, bg, hyp_w, temp);

    hgemm_k<0><<<dim3(8, 16, 12), 256, SM_PIPE>>>(nullptr, nullptr);

    zero2_k<<<2048, 256>>>(out2);

    fused_attn6_k<<<dim3(32, H_, B_), 512, SM_FUSED>>>(out2);

    amean_red_dummy:;
    hgemm_k<3><<<dim3(8, 16, 1), 256, SM_PIPE>>>(out, bo);
}

// round 13
// speedup vs baseline: 1.1500x; 1.1500x over previous
#include <cuda_runtime.h>
#include <cuda_fp16.h>
#include <cstdint>

#define S_ 4
#define B_ 2
#define N_ 1024
#define D_ 1024
#define H_ 16
#define DH_ 64

// ---------------- device scratch (no allocations allowed) -------------------
__device__ __half g_xh[B_ * N_ * D_];                       // 4MB
__device__ __half g_wh[13 * 1024 * 1024];                   // Wq(0-3) Wk(4-7) Wv(8-11) Wo(12)
__device__ __half g_qh[S_ * B_ * N_ * D_];                  // 16MB
__device__ __half g_kh[S_ * B_ * N_ * D_];                  // 16MB
__device__ __half g_vh[S_ * B_ * N_ * D_];                  // 16MB
__device__ __half g_combh[B_ * N_ * D_];                    // 4MB
__device__ float g_meanx[B_ * D_];
__device__ float g_scalars[16];  // [0..7]=gw*coh (b*4+s), [8..11]=gw/H, [12]=scale/temp

// ---------------- helpers ----------------------------------------------------
__device__ __forceinline__ uint32_t smem_u32(const void* p) {
    uint32_t a;
    asm("{ .reg .u64 t; cvta.to.shared.u64 t, %1; cvt.u32.u64 %0, t; }" : "=r"(a) : "l"(p));
    return a;
}
__device__ __forceinline__ void cp16h(uint32_t dst, const __half* src) {
    asm volatile("cp.async.ca.shared.global [%0], [%1], 16;" :: "r"(dst), "l"(src) : "memory");
}
__device__ __forceinline__ void ldm4(uint32_t* r, uint32_t addr) {
    asm volatile("ldmatrix.sync.aligned.m8n8.x4.shared.b16 {%0,%1,%2,%3}, [%4];"
        : "=r"(r[0]), "=r"(r[1]), "=r"(r[2]), "=r"(r[3]) : "r"(addr));
}
__device__ __forceinline__ void ldm2t(uint32_t* r, uint32_t addr) {
    asm volatile("ldmatrix.sync.aligned.m8n8.x2.trans.shared.b16 {%0,%1}, [%2];"
        : "=r"(r[0]), "=r"(r[1]) : "r"(addr));
}
__device__ __forceinline__ void mma16816(float* d, const uint32_t* a, uint32_t b0, uint32_t b1) {
    asm volatile(
        "mma.sync.aligned.m16n8k16.row.col.f32.f16.f16.f32 "
        "{%0,%1,%2,%3}, {%4,%5,%6,%7}, {%8,%9}, {%0,%1,%2,%3};"
        : "+f"(d[0]), "+f"(d[1]), "+f"(d[2]), "+f"(d[3])
        : "r"(a[0]), "r"(a[1]), "r"(a[2]), "r"(a[3]), "r"(b0), "r"(b1));
}
__device__ __forceinline__ uint32_t h2u(__half2 h) { return *(uint32_t*)&h; }
__device__ __forceinline__ __half2 u2h(uint32_t u) { return *(__half2*)&u; }

// ---------------- merged prep (fp16 round) + colmean -------------------------
__global__ void prepcol_k(const float* __restrict__ x, const float* __restrict__ Wq,
                          const float* __restrict__ Wk, const float* __restrict__ Wv,
                          const float* __restrict__ Wo) {
    __shared__ float part[8][33];
    if (blockIdx.x < 15360) {
        long long idx = ((long long)blockIdx.x * 256 + threadIdx.x) * 4;
        const float* src; __half* dst; long long off;
        if (idx < 2097152)        { src = x;  off = idx;            dst = g_xh; }
        else if (idx < 6291456)   { src = Wq; off = idx - 2097152;  dst = g_wh; }
        else if (idx < 10485760)  { src = Wk; off = idx - 6291456;  dst = g_wh + 4194304; }
        else if (idx < 14680064)  { src = Wv; off = idx - 10485760; dst = g_wh + 8388608; }
        else                      { src = Wo; off = idx - 14680064; dst = g_wh + 12582912; }
        float4 v = *(const float4*)(src + off);
        __half2 h0 = __floats2half2_rn(v.x, v.y), h1 = __floats2half2_rn(v.z, v.w);
        uint2 o; o.x = h2u(h0); o.y = h2u(h1);
        *(uint2*)(dst + off) = o;
    } else {
        int bid = blockIdx.x - 15360;
        int col = bid * 32 + (threadIdx.x & 31);
        int chunk = threadIdx.x >> 5;
        int b = col >> 10, d = col & 1023;
        float sum = 0.f;
        const float* xp = x + (long long)b * N_ * D_ + d + (long long)(chunk * 128) * D_;
        #pragma unroll 8
        for (int n = 0; n < 128; n++) sum += xp[(long long)n * D_];
        part[chunk][threadIdx.x & 31] = sum;
        __syncthreads();
        if (threadIdx.x < 32) {
            float s = 0.f;
            #pragma unroll
            for (int c = 0; c < 8; c++) s += part[c][threadIdx.x];
            g_meanx[bid * 32 + threadIdx.x] = s * (1.0f / N_);
        }
    }
}

// ---------------- gate: coh, gw, fused scalars ------------------------------
__global__ void gate_k(const float* __restrict__ Wg, const float* __restrict__ bg,
                       const float* __restrict__ hyp_w, const float* __restrict__ temp_p) {
    __shared__ float cohs[8];
    int tid = threadIdx.x;
    int w = tid >> 5, lane = tid & 31;
    if (w < 8) {
        int b = w >> 2, s = w & 3;
        float sum = 0.f;
        for (int d = lane; d < D_; d += 32)
            sum += g_meanx[b * D_ + d] * Wg[s * D_ + d];
        for (int o = 16; o; o >>= 1) sum += __shfl_xor_sync(0xffffffffu, sum, o);
        if (lane == 0) cohs[w] = 1.0f / (1.0f + expf(-(sum + bg[s])));
    }
    __syncthreads();
    if (tid == 0) {
        float t = fminf(fmaxf(temp_p[0], 0.1f), 10.0f);
        float e[S_], mx = -1e30f;
        for (int s = 0; s < S_; s++) { e[s] = hyp_w[s] / t; mx = fmaxf(mx, e[s]); }
        float den = 0.f;
        for (int s = 0; s < S_; s++) { e[s] = expf(e[s] - mx); den += e[s]; }
        for (int s = 0; s < S_; s++) {
            float gw = e[s] / den;
            g_scalars[8 + s] = gw / (float)H_;
            for (int b = 0; b < B_; b++)
                g_scalars[b * 4 + s] = gw * cohs[b * 4 + s];
        }
        g_scalars[12] = 0.125f / t;   // DH^-0.5 / temp
    }
}

// ---------------- zero amean half of d_out -----------------------------------
__global__ void zero2_k(float* __restrict__ outp) {
    long long idx = ((long long)blockIdx.x * 256 + threadIdx.x) * 4;
    *(float4*)(outp + idx) = make_float4(0.f, 0.f, 0.f, 0.f);
}

// ---------------- fp16 HMMA GEMM (projections): 2-stage (R8-proven) ---------
template<int MODE>
__global__ void __launch_bounds__(256) hgemm_k(float* __restrict__ outp,
                                               const float* __restrict__ bias)
{
    constexpr int STAGE = 256 * 128;
    extern __shared__ char smem[];
    uint32_t smb = smem_u32(smem);

    int tid = threadIdx.x, lane = tid & 31, wid = tid >> 5;
    int warpM = wid & 3, warpN = wid >> 2;
    int n0 = blockIdx.x * 128, m0 = blockIdx.y * 128, z = blockIdx.z;

    const __half *Ag, *Bg;
    if (MODE == 0) { Ag = g_xh; Bg = g_wh + ((long long)z << 20); }
    else           { Ag = g_combh; Bg = g_wh + (12LL << 20); }

    float acc[2][8][4];
    #pragma unroll
    for (int mf = 0; mf < 2; mf++)
        #pragma unroll
        for (int nf = 0; nf < 8; nf++)
            #pragma unroll
            for (int i = 0; i < 4; i++) acc[mf][nf][i] = 0.f;

    auto issue = [&](int t) {
        const __half* ap = Ag + (long long)m0 * 1024 + t * 64;
        const __half* bp = Bg + (long long)n0 * 1024 + t * 64;
        uint32_t sa  = smb + (t & 1) * STAGE;
        uint32_t sbb = sa + 128 * 128;
        #pragma unroll
        for (int i = 0; i < 4; i++) {
            int c = tid + 256 * i, row = c >> 3, ch = c & 7;
            cp16h(sa + ((row * 128 + ch * 16) ^ ((row & 7) << 4)),
                  ap + (long long)row * 1024 + ch * 8);
        }
        #pragma unroll
        for (int i = 0; i < 4; i++) {
            int c = tid + 256 * i, row = c >> 3, ch = c & 7;
            cp16h(sbb + ((row * 128 + ch * 16) ^ ((row & 7) << 4)),
                  bp + (long long)row * 1024 + ch * 8);
        }
        asm volatile("cp.async.commit_group;" ::: "memory");
    };

    issue(0);
    for (int t = 0; t < 16; t++) {
        if (t + 1 < 16) {
            issue(t + 1);
            asm volatile("cp.async.wait_group 1;" ::: "memory");
        } else {
            asm volatile("cp.async.wait_group 0;" ::: "memory");
        }
        __syncthreads();
        uint32_t sa = smb + (t & 1) * STAGE, sbb = sa + 128 * 128;
        #pragma unroll
        for (int kk = 0; kk < 4; kk++) {
            uint32_t af[2][4], bf[4][4];
            #pragma unroll
            for (int mf = 0; mf < 2; mf++) {
                int row = warpM * 32 + mf * 16 + (lane & 15);
                uint32_t off = row * 128 + kk * 32 + ((lane >> 4) << 4);
                ldm4(af[mf], sa + (off ^ ((row & 7) << 4)));
            }
            #pragma unroll
            for (int nb = 0; nb < 4; nb++) {
                int row = warpN * 64 + nb * 16 + (lane & 15);
                uint32_t off = row * 128 + kk * 32 + ((lane >> 4) << 4);
                ldm4(bf[nb], sbb + (off ^ ((row & 7) << 4)));
            }
            #pragma unroll
            for (int mf = 0; mf < 2; mf++)
                #pragma unroll
                for (int nf = 0; nf < 8; nf++)
                    mma16816(acc[mf][nf], af[mf], bf[nf >> 1][nf & 1], bf[nf >> 1][(nf & 1) + 2]);
        }
        __syncthreads();
    }

    int r4 = lane >> 2, c4l = lane & 3;
    if (MODE == 0) {
        int w_ = z >> 2, s_ = z & 3;
        __half* C = (w_ == 0 ? g_qh : (w_ == 1 ? g_kh : g_vh)) + ((long long)s_ << 21);
        #pragma unroll
        for (int mf = 0; mf < 2; mf++)
            #pragma unroll
            for (int nf = 0; nf < 8; nf++)
                #pragma unroll
                for (int hf = 0; hf < 2; hf++) {
                    int row = m0 + warpM * 32 + mf * 16 + r4 + hf * 8;
                    int col = n0 + warpN * 64 + nf * 8 + c4l * 2;
                    __half2 hv = __floats2half2_rn(acc[mf][nf][hf * 2], acc[mf][nf][hf * 2 + 1]);
                    *(__half2*)(C + (long long)row * 1024 + col) = hv;
                }
    } else {
        #pragma unroll
        for (int mf = 0; mf < 2; mf++)
            #pragma unroll
            for (int nf = 0; nf < 8; nf++)
                #pragma unroll
                for (int hf = 0; hf < 2; hf++) {
                    int row = m0 + warpM * 32 + mf * 16 + r4 + hf * 8;
                    int col = n0 + warpN * 64 + nf * 8 + c4l * 2;
                    float2 o;
                    o.x = acc[mf][nf][hf * 2]     + bias[col];
                    o.y = acc[mf][nf][hf * 2 + 1] + bias[col + 1];
                    *(float2*)(outp + (long long)row * 1024 + col) = o;
                }
    }
}

// ---------------- fused attention v7: 256 thr, ring, warp-owned PV slices ----
// grid (32, 16, 2) = (it, h, b). smem layout identical to v5 (231,168 B).
#define AME_SCALE 256.0f
__global__ void __launch_bounds__(256) fused_attn7_k(float* __restrict__ amean_out) {
    extern __shared__ char smem[];
    uint32_t smb = smem_u32(smem);
    const uint32_t STRIP = smb;
    const uint32_t AMEH  = smb + 65536;
    const uint32_t RING  = smb + 131584;
    float* lred = (float*)(smem + 229888);
    float* linv = (float*)(smem + 231040);

    int tid = threadIdx.x, lane = tid & 31, wid = tid >> 5;
    int it = blockIdx.x, h = blockIdx.y, b = blockIdx.z;
    int i0 = it * 32;
    int r4 = lane >> 2, c4l = lane & 3, c2 = c4l * 2;

    for (int i = tid; i < 16512; i += 256)
        asm volatile("st.shared.b32 [%0], %1;" :: "r"(AMEH + i * 4), "r"(0u));
    __syncthreads();

    float alpha = g_scalars[12];
    float oacc[2][8][4];
    #pragma unroll
    for (int mf = 0; mf < 2; mf++)
        #pragma unroll
        for (int nf = 0; nf < 8; nf++)
            #pragma unroll
            for (int i = 0; i < 4; i++) oacc[mf][nf][i] = 0.f;

    auto issue_g = [&](int g) {
        if (g < 68) {
            int s = g / 17, t = g - s * 17;
            long long sbase = ((long long)(s * B_ + b)) << 20;
            uint32_t dst = RING + (uint32_t)(g % 6) * 16384;
            if (t == 0) {
                const __half* src = g_qh + sbase + (long long)i0 * 1024 + h * 64;
                int r = tid >> 3, c = tid & 7;
                cp16h(dst + ((r * 128 + c * 16) ^ ((r & 7) << 4)),
                      src + (long long)r * 1024 + c * 8);
            } else {
                const __half* base = ((t <= 8) ? g_kh : g_vh) + sbase + h * 64;
                int jt = (t <= 8) ? (t - 1) : (t - 9);
                const __half* src = base + (long long)jt * 128 * 1024;
                #pragma unroll
                for (int i = 0; i < 4; i++) {
                    int idx = tid + 256 * i, r = idx >> 3, c = idx & 7;
                    cp16h(dst + ((r * 128 + c * 16) ^ ((r & 7) << 4)),
                          src + (long long)r * 1024 + c * 8);
                }
            }
        }
        asm volatile("cp.async.commit_group;" ::: "memory");
    };

    for (int g = 0; g < 5; g++) issue_g(g);
    int gi = 5;

    for (int s = 0; s < S_; s++) {
        float ga = g_scalars[8 + s], wsb = g_scalars[b * 4 + s];
        int gbase = s * 17;

        asm volatile("cp.async.wait_group 4;" ::: "memory");
        __syncthreads();
        issue_g(gi++);
        uint32_t qf[4][2][4];
        {
            uint32_t qslot = RING + (uint32_t)(gbase % 6) * 16384;
            #pragma unroll
            for (int kk = 0; kk < 4; kk++)
                #pragma unroll
                for (int mf = 0; mf < 2; mf++) {
                    int r = mf * 16 + (lane & 15);
                    ldm4(qf[kk][mf],
                         qslot + ((r * 128 + kk * 32 + ((lane >> 4) << 4)) ^ ((r & 7) << 4)));
                }
        }

        // ---- SCORE rounds ----
        float l_part[4] = {0.f, 0.f, 0.f, 0.f};
        for (int jt = 0; jt < 8; jt++) {
            asm volatile("cp.async.wait_group 4;" ::: "memory");
            __syncthreads();
            issue_g(gi++);
            uint32_t kb = RING + (uint32_t)((gbase + 1 + jt) % 6) * 16384;
            float sacc[2][2][4];
            #pragma unroll
            for (int mf = 0; mf < 2; mf++)
                #pragma unroll
                for (int nb = 0; nb < 2; nb++)
                    #pragma unroll
                    for (int i = 0; i < 4; i++) sacc[mf][nb][i] = 0.f;
            #pragma unroll
            for (int kk = 0; kk < 4; kk++) {
                uint32_t bf[4];
                int r = wid * 16 + (lane & 15);
                ldm4(bf, kb + ((r * 128 + kk * 32 + ((lane >> 4) << 4)) ^ ((r & 7) << 4)));
                #pragma unroll
                for (int mf = 0; mf < 2; mf++) {
                    mma16816(sacc[mf][0], qf[kk][mf], bf[0], bf[2]);
                    mma16816(sacc[mf][1], qf[kk][mf], bf[1], bf[3]);
                }
            }
            #pragma unroll
            for (int mf = 0; mf < 2; mf++)
                #pragma unroll
                for (int nb = 0; nb < 2; nb++)
                    #pragma unroll
                    for (int hf = 0; hf < 2; hf++) {
                        float e0 = __expf(sacc[mf][nb][hf * 2]     * alpha);
                        float e1 = __expf(sacc[mf][nb][hf * 2 + 1] * alpha);
                        l_part[mf * 2 + hf] += e0 + e1;
                        int row = mf * 16 + r4 + hf * 8;
                        uint32_t byte = (uint32_t)((jt * 128 + wid * 16 + nb * 8 + c2) * 2);
                        asm volatile("st.shared.b32 [%0], %1;"
                            :: "r"(STRIP + row * 2048 + (byte ^ ((row & 7) << 4))),
                               "r"(h2u(__floats2half2_rn(e0, e1))));
                    }
        }

        // ---- l reduce ----
        #pragma unroll
        for (int i = 0; i < 4; i++) {
            l_part[i] += __shfl_xor_sync(0xffffffffu, l_part[i], 1);
            l_part[i] += __shfl_xor_sync(0xffffffffu, l_part[i], 2);
        }
        if (c4l == 0)
            #pragma unroll
            for (int i = 0; i < 4; i++) lred[(i * 8 + r4) * 9 + wid] = l_part[i];
        __syncthreads();
        if (tid < 32) {
            float sm = 0.f;
            #pragma unroll
            for (int w = 0; w < 8; w++) sm += lred[tid * 9 + w];
            linv[tid] = 1.0f / sm;
        }
        __syncthreads();

        __half2 sc[2][2], gah[2][2];
        #pragma unroll
        for (int mf = 0; mf < 2; mf++) {
            float li0 = linv[mf * 16 + r4], li1 = linv[mf * 16 + r4 + 8];
            sc[mf][0]  = __float2half2_rn(wsb * li0);
            sc[mf][1]  = __float2half2_rn(wsb * li1);
            gah[mf][0] = __float2half2_rn(ga * li0 * AME_SCALE);
            gah[mf][1] = __float2half2_rn(ga * li1 * AME_SCALE);
        }

        // ---- PV rounds: each warp owns jloc = wid*16, all 64 d-cols ----
        int jloc = wid * 16;
        for (int jt = 0; jt < 8; jt++) {
            asm volatile("cp.async.wait_group 4;" ::: "memory");
            __syncthreads();
            issue_g(gi++);
            uint32_t vb = RING + (uint32_t)((gbase + 9 + jt) % 6) * 16384;

            uint32_t af[2][4];
            #pragma unroll
            for (int mf = 0; mf < 2; mf++) {
                int r = mf * 16 + (lane & 15);
                uint32_t byte = (uint32_t)((jt * 128 + jloc) * 2) + ((lane >> 4) << 4);
                ldm4(af[mf], STRIP + r * 2048 + (byte ^ ((r & 7) << 4)));
            }
            // amean RMW: this warp's distinct 16-col slice
            #pragma unroll
            for (int mf = 0; mf < 2; mf++) {
                int row0 = mf * 16 + r4, row1 = row0 + 8;
                int colb = jt * 128 + jloc + c2;
                uint32_t a00 = AMEH + (uint32_t)(row0 * 1032 + colb) * 2;
                uint32_t a10 = AMEH + (uint32_t)(row1 * 1032 + colb) * 2;
                uint32_t old;
                asm volatile("ld.shared.b32 %0, [%1];" : "=r"(old) : "r"(a00));
                asm volatile("st.shared.b32 [%0], %1;" :: "r"(a00),
                    "r"(h2u(__hfma2(u2h(af[mf][0]), gah[mf][0], u2h(old)))));
                asm volatile("ld.shared.b32 %0, [%1];" : "=r"(old) : "r"(a10));
                asm volatile("st.shared.b32 [%0], %1;" :: "r"(a10),
                    "r"(h2u(__hfma2(u2h(af[mf][1]), gah[mf][1], u2h(old)))));
                asm volatile("ld.shared.b32 %0, [%1];" : "=r"(old) : "r"(a00 + 16));
                asm volatile("st.shared.b32 [%0], %1;" :: "r"(a00 + 16),
                    "r"(h2u(__hfma2(u2h(af[mf][2]), gah[mf][0], u2h(old)))));
                asm volatile("ld.shared.b32 %0, [%1];" : "=r"(old) : "r"(a10 + 16));
                asm volatile("st.shared.b32 [%0], %1;" :: "r"(a10 + 16),
                    "r"(h2u(__hfma2(u2h(af[mf][3]), gah[mf][1], u2h(old)))));
            }
            #pragma unroll
            for (int mf = 0; mf < 2; mf++) {
                af[mf][0] = h2u(__hmul2(u2h(af[mf][0]), sc[mf][0]));
                af[mf][1] = h2u(__hmul2(u2h(af[mf][1]), sc[mf][1]));
                af[mf][2] = h2u(__hmul2(u2h(af[mf][2]), sc[mf][0]));
                af[mf][3] = h2u(__hmul2(u2h(af[mf][3]), sc[mf][1]));
            }
            int kr = jloc + (lane & 7) + ((lane >> 3) & 1) * 8;
            #pragma unroll
            for (int nf = 0; nf < 8; nf++) {
                uint32_t bf[2];
                ldm2t(bf, vb + ((kr * 128 + nf * 16) ^ ((kr & 7) << 4)));
                #pragma unroll
                for (int mf = 0; mf < 2; mf++)
                    mma16816(oacc[mf][nf], af[mf], bf[0], bf[1]);
            }
        }
    } // s
    __syncthreads();

    // ---- O: 8 warp partials by logical (row,col), flat reduce ----
    {
        float* scr = (float*)(smem + 131584);   // 64KB, ring is dead
        #pragma unroll
        for (int mf = 0; mf < 2; mf++)
            #pragma unroll
            for (int nf = 0; nf < 8; nf++)
                #pragma unroll
                for (int i = 0; i < 4; i++) {
                    int row = mf * 16 + r4 + (i >> 1) * 8;
                    int col = nf * 8 + c2 + (i & 1);
                    scr[wid * 2048 + row * 64 + col] = oacc[mf][nf][i];
                }
        __syncthreads();
        int row = tid >> 3, colg = (tid & 7) * 8;
        #pragma unroll
        for (int c = 0; c < 8; c += 2) {
            float v0 = 0.f, v1 = 0.f;
            #pragma unroll
            for (int w = 0; w < 8; w++) {
                v0 += scr[w * 2048 + row * 64 + colg + c];
                v1 += scr[w * 2048 + row * 64 + colg + c + 1];
            }
            __half2 hv = __floats2half2_rn(v0, v1);
            *(__half2*)(g_combh + ((long long)b << 20)
                        + (long long)(i0 + row) * 1024 + h * 64 + colg + c) = hv;
        }
    }

    // ---- amean flush: fp16(x256) -> f32 red.add into d_out second half ----
    {
        const float inv_s = 1.0f / AME_SCALE;
        for (int i = tid; i < 8192; i += 256) {
            int row = i >> 8, cc = (i & 255) * 4;
            uint2 u;
            asm volatile("ld.shared.v2.b32 {%0,%1}, [%2];"
                : "=r"(u.x), "=r"(u.y) : "r"(AMEH + (uint32_t)(row * 1032 + cc) * 2));
            float2 f0 = __half22float2(u2h(u.x)), f1 = __half22float2(u2h(u.y));
            float* dst = amean_out + ((long long)(b * 1024 + i0 + row)) * 1024 + cc;
            asm volatile("red.global.add.f32 [%0], %1;" :: "l"(dst),     "f"(f0.x * inv_s));
            asm volatile("red.global.add.f32 [%0], %1;" :: "l"(dst + 1), "f"(f0.y * inv_s));
            asm volatile("red.global.add.f32 [%0], %1;" :: "l"(dst + 2), "f"(f1.x * inv_s));
            asm volatile("red.global.add.f32 [%0], %1;" :: "l"(dst + 3), "f"(f1.y * inv_s));
        }
    }
}

// ---------------- launch ----------------------------------------------------
extern "C" void kernel_launch(void* const* d_in, const int* in_sizes, int n_in,
                              void* d_out, int out_size) {
    const float* x     = (const float*)d_in[0];
    const float* Wq    = (const float*)d_in[1];
    const float* Wk    = (const float*)d_in[2];
    const float* Wv    = (const float*)d_in[3];
    const float* Wg    = (const float*)d_in[4];
    const float* bg    = (const float*)d_in[5];
    const float* Wo    = (const float*)d_in[6];
    const float* bo    = (const float*)d_in[7];
    const float* hyp_w = (const float*)d_in[8];
    const float* temp  = (const float*)d_in[9];
    float* out = (float*)d_out;
    float* out2 = out + (long long)B_ * N_ * D_;

    const int SM_PIPE  = 65536;
    const int SM_FUSED = 231168;

    cudaFuncSetAttribute(hgemm_k<0>, cudaFuncAttributeMaxDynamicSharedMemorySize, SM_PIPE);
    cudaFuncSetAttribute(hgemm_k<3>, cudaFuncAttributeMaxDynamicSharedMemorySize, SM_PIPE);
    cudaFuncSetAttribute(fused_attn7_k, cudaFuncAttributeMaxDynamicSharedMemorySize, SM_FUSED);

    zero2_k<<<2048, 256>>>(out2);
    prepcol_k<<<15424, 256>>>(x, Wq, Wk, Wv, Wo);
    gate_k<<<1, 256>>>(Wg, bg, hyp_w, temp);

    hgemm_k<0><<<dim3(8, 16, 12), 256, SM_PIPE>>>(nullptr, nullptr);

    fused_attn7_k<<<dim3(32, H_, B_), 256, SM_FUSED>>>(out2);

    hgemm_k<3><<<dim3(8, 16, 1), 256, SM_PIPE>>>(out, bo);
}